// round 1
// baseline (speedup 1.0000x reference)
#include <cuda_runtime.h>

#define BB 4
#define NN 4096
#define CC 1024
#define HH 16
#define DH 64
#define RR 266
#define EPSF 1e-3f
#define BHN (BB*HH)   // 64

// ---------------- scratch (device globals; no allocation allowed) ----------
__device__ float g_q [BB*NN*CC];          // 16.7M
__device__ float g_k [BB*NN*CC];
__device__ float g_v [BB*NN*CC];
__device__ float g_qp[(size_t)BHN*NN*RR]; // 69.7M
__device__ float g_kp[(size_t)BHN*NN*RR];
__device__ float g_ksum[BHN*RR];
__device__ float g_dinv[BHN*NN];
__device__ float g_kv[BHN*RR*DH];
__device__ float g_om[BB*NN*CC];

// ---------------- 128x128x16 register-tiled SGEMM (M,N,K % 128/16 == 0) ----
__global__ __launch_bounds__(256) void sgemm128(
    const float* __restrict__ A, const float* __restrict__ B,
    const float* __restrict__ bias, float* __restrict__ C,
    int M, int N, int K)
{
    __shared__ float As[16][132];   // [k][m], padded
    __shared__ float Bs[16][128];   // [k][n]
    const int tid = threadIdx.x;
    const int tx = tid & 15, ty = tid >> 4;
    const int row0 = blockIdx.y * 128, col0 = blockIdx.x * 128;

    float acc[8][8] = {};

    for (int k0 = 0; k0 < K; k0 += 16) {
        #pragma unroll
        for (int t = 0; t < 2; t++) {
            int f = tid + t * 256;               // float4 index in [0,512)
            int arow = f >> 2, ak = (f & 3) * 4;
            float4 va = *(const float4*)&A[(size_t)(row0 + arow) * K + k0 + ak];
            As[ak + 0][arow] = va.x;
            As[ak + 1][arow] = va.y;
            As[ak + 2][arow] = va.z;
            As[ak + 3][arow] = va.w;
            int brow = f >> 5, bc = (f & 31) * 4;
            *(float4*)&Bs[brow][bc] =
                *(const float4*)&B[(size_t)(k0 + brow) * N + col0 + bc];
        }
        __syncthreads();
        #pragma unroll
        for (int k = 0; k < 16; k++) {
            float ar[8], br[8];
            *(float4*)&ar[0] = *(const float4*)&As[k][ty * 8];
            *(float4*)&ar[4] = *(const float4*)&As[k][ty * 8 + 4];
            *(float4*)&br[0] = *(const float4*)&Bs[k][tx * 8];
            *(float4*)&br[4] = *(const float4*)&Bs[k][tx * 8 + 4];
            #pragma unroll
            for (int i = 0; i < 8; i++)
                #pragma unroll
                for (int j = 0; j < 8; j++)
                    acc[i][j] += ar[i] * br[j];
        }
        __syncthreads();
    }

    #pragma unroll
    for (int i = 0; i < 8; i++) {
        int r = row0 + ty * 8 + i;
        #pragma unroll
        for (int j = 0; j < 8; j += 4) {
            int c = col0 + tx * 8 + j;
            float4 o;
            o.x = acc[i][j];     o.y = acc[i][j + 1];
            o.z = acc[i][j + 2]; o.w = acc[i][j + 3];
            if (bias) {
                o.x += bias[c];     o.y += bias[c + 1];
                o.z += bias[c + 2]; o.w += bias[c + 3];
            }
            *(float4*)&C[(size_t)r * N + c] = o;
        }
    }
}

// ---------------- feature map: qp/kp = relu(head @ proj^T) + eps -----------
// grid (ceil(R/64)=5, N/64=64, 2*BHN=128), block 256
__global__ __launch_bounds__(256) void featmap_kernel(const float* __restrict__ proj)
{
    const int z = blockIdx.z;
    const int which = z >> 6;            // 0 -> q, 1 -> k
    const int bh = z & 63;
    const int b = bh >> 4, h = bh & 15;
    const float* __restrict__ src = which ? g_k : g_q;
    float* __restrict__ dst = which ? g_kp : g_qp;
    const int n0 = blockIdx.y * 64;
    const int r0 = blockIdx.x * 64;

    __shared__ float Ast[64][65];   // [d][i]
    __shared__ float Bs[64][65];    // [d][rl]
    const int tid = threadIdx.x;

    #pragma unroll
    for (int t = 0; t < 16; t++) {
        int e = tid + t * 256;
        int i = e >> 6, d = e & 63;
        Ast[d][i] = src[(size_t)(b * NN + n0 + i) * CC + h * 64 + d];
        int rr = r0 + i;
        Bs[d][i] = (rr < RR) ? proj[rr * 64 + d] : 0.0f;
    }
    __syncthreads();

    const int tx = tid & 15, ty = tid >> 4;
    float acc[4][4] = {};
    #pragma unroll 16
    for (int k = 0; k < 64; k++) {
        float a[4], bq[4];
        #pragma unroll
        for (int i = 0; i < 4; i++) a[i] = Ast[k][ty * 4 + i];
        #pragma unroll
        for (int j = 0; j < 4; j++) bq[j] = Bs[k][tx * 4 + j];
        #pragma unroll
        for (int i = 0; i < 4; i++)
            #pragma unroll
            for (int j = 0; j < 4; j++)
                acc[i][j] += a[i] * bq[j];
    }

    #pragma unroll
    for (int i = 0; i < 4; i++) {
        int n = n0 + ty * 4 + i;
        #pragma unroll
        for (int j = 0; j < 4; j++) {
            int r = r0 + tx * 4 + j;
            if (r < RR) {
                float v = acc[i][j];
                v = v > 0.0f ? v : 0.0f;
                dst[((size_t)bh * NN + n) * RR + r] = v + EPSF;
            }
        }
    }
}

// ---------------- k_sum = sum_n kp ------------------------------------------
// grid (BHN, 3, NN/256=16), block 128
__global__ void ksum_kernel()
{
    const int bh = blockIdx.x;
    const int r = blockIdx.y * 128 + threadIdx.x;
    if (r >= RR) return;
    const int n0 = blockIdx.z * 256;
    const float* __restrict__ base = g_kp + (size_t)bh * NN * RR;
    float s0 = 0.f, s1 = 0.f, s2 = 0.f, s3 = 0.f;
    #pragma unroll 4
    for (int n = n0; n < n0 + 256; n += 4) {
        s0 += base[(size_t)(n + 0) * RR + r];
        s1 += base[(size_t)(n + 1) * RR + r];
        s2 += base[(size_t)(n + 2) * RR + r];
        s3 += base[(size_t)(n + 3) * RR + r];
    }
    atomicAdd(&g_ksum[bh * RR + r], (s0 + s1) + (s2 + s3));
}

// ---------------- d_inv = 1 / (qp . k_sum) ----------------------------------
// one warp per (bh, n); grid 32768 blocks x 256 threads (8 warps)
__global__ void dinv_kernel()
{
    const int gw = (blockIdx.x * blockDim.x + threadIdx.x) >> 5;
    const int lane = threadIdx.x & 31;
    const int bh = gw >> 12;      // / 4096
    const int n = gw & 4095;
    const float* __restrict__ qrow = g_qp + ((size_t)bh * NN + n) * RR;
    const float* __restrict__ ks = g_ksum + bh * RR;
    float s = 0.f;
    for (int r = lane; r < RR; r += 32) s += qrow[r] * ks[r];
    #pragma unroll
    for (int o = 16; o; o >>= 1) s += __shfl_xor_sync(0xffffffffu, s, o);
    if (lane == 0) g_dinv[(size_t)bh * NN + n] = 1.0f / s;
}

// ---------------- kv = kp^T @ v per head (R x HC) ----------------------------
// grid (BHN, ceil(R/64)=5), block 256; thread owns 2 r-rows x 8 cols
__global__ __launch_bounds__(256) void kv_kernel()
{
    const int bh = blockIdx.x;
    const int b = bh >> 4, h = bh & 15;
    const int r0 = blockIdx.y * 64;

    __shared__ float kps[64][65];   // [nn][rl]
    __shared__ float vs[64][64];    // [nn][c]
    const int tid = threadIdx.x;
    const int rlo = tid >> 3;            // 0..31
    const int c0 = (tid & 7) * 8;

    float acc0[8] = {}, acc1[8] = {};
    const float* __restrict__ kpb = g_kp + (size_t)bh * NN * RR;
    const float* __restrict__ vb  = g_v + (size_t)b * NN * CC + h * 64;

    for (int n0 = 0; n0 < NN; n0 += 64) {
        #pragma unroll
        for (int t = 0; t < 16; t++) {
            int e = tid + t * 256;
            int nn = e >> 6, rl = e & 63;
            int rr = r0 + rl;
            kps[nn][rl] = (rr < RR) ? kpb[(size_t)(n0 + nn) * RR + rr] : 0.0f;
        }
        #pragma unroll
        for (int t = 0; t < 16; t++) {
            int e = tid + t * 256;
            int nn = e >> 6, c = e & 63;
            vs[nn][c] = vb[(size_t)(n0 + nn) * CC + c];
        }
        __syncthreads();
        #pragma unroll 8
        for (int nn = 0; nn < 64; nn++) {
            float a0 = kps[nn][rlo];
            float a1 = kps[nn][rlo + 32];
            float4 v0 = *(const float4*)&vs[nn][c0];
            float4 v1 = *(const float4*)&vs[nn][c0 + 4];
            acc0[0] += a0 * v0.x; acc0[1] += a0 * v0.y;
            acc0[2] += a0 * v0.z; acc0[3] += a0 * v0.w;
            acc0[4] += a0 * v1.x; acc0[5] += a0 * v1.y;
            acc0[6] += a0 * v1.z; acc0[7] += a0 * v1.w;
            acc1[0] += a1 * v0.x; acc1[1] += a1 * v0.y;
            acc1[2] += a1 * v0.z; acc1[3] += a1 * v0.w;
            acc1[4] += a1 * v1.x; acc1[5] += a1 * v1.y;
            acc1[6] += a1 * v1.z; acc1[7] += a1 * v1.w;
        }
        __syncthreads();
    }

    int rr0 = r0 + rlo, rr1 = rr0 + 32;
    if (rr0 < RR) {
        #pragma unroll
        for (int j = 0; j < 8; j++)
            g_kv[((size_t)bh * RR + rr0) * 64 + c0 + j] = acc0[j];
    }
    if (rr1 < RR) {
        #pragma unroll
        for (int j = 0; j < 8; j++)
            g_kv[((size_t)bh * RR + rr1) * 64 + c0 + j] = acc1[j];
    }
}

// ---------------- qkv = qp @ kv, scaled by d_inv, write merged layout -------
// grid (BHN, NN/64=64), block 256
__global__ __launch_bounds__(256) void qkv_kernel()
{
    const int bh = blockIdx.x;
    const int b = bh >> 4, h = bh & 15;
    const int n0 = blockIdx.y * 64;

    __shared__ float qpsT[64][65];  // [kk][i]
    __shared__ float kvs[64][64];   // [kk][c]
    const int tid = threadIdx.x;
    const int tx = tid & 15, ty = tid >> 4;

    float acc[4][4] = {};
    const float* __restrict__ qpb = g_qp + (size_t)bh * NN * RR;
    const float* __restrict__ kvb = g_kv + (size_t)bh * RR * 64;

    for (int k0 = 0; k0 < RR; k0 += 64) {
        #pragma unroll
        for (int t = 0; t < 16; t++) {
            int e = tid + t * 256;
            int i = e >> 6, kk = e & 63;
            int kr = k0 + kk;
            qpsT[kk][i] = (kr < RR) ? qpb[(size_t)(n0 + i) * RR + kr] : 0.0f;
        }
        #pragma unroll
        for (int t = 0; t < 16; t++) {
            int e = tid + t * 256;
            int kk = e >> 6, c = e & 63;
            int kr = k0 + kk;
            kvs[kk][c] = (kr < RR) ? kvb[(size_t)kr * 64 + c] : 0.0f;
        }
        __syncthreads();
        #pragma unroll 16
        for (int k = 0; k < 64; k++) {
            float a[4], bq[4];
            #pragma unroll
            for (int i = 0; i < 4; i++) a[i] = qpsT[k][ty * 4 + i];
            #pragma unroll
            for (int j = 0; j < 4; j++) bq[j] = kvs[k][tx * 4 + j];
            #pragma unroll
            for (int i = 0; i < 4; i++)
                #pragma unroll
                for (int j = 0; j < 4; j++)
                    acc[i][j] += a[i] * bq[j];
        }
        __syncthreads();
    }

    #pragma unroll
    for (int i = 0; i < 4; i++) {
        int n = n0 + ty * 4 + i;
        float di = g_dinv[(size_t)bh * NN + n];
        #pragma unroll
        for (int j = 0; j < 4; j++) {
            int c = tx * 4 + j;
            g_om[(size_t)(b * NN + n) * CC + h * 64 + c] = acc[i][j] * di;
        }
    }
}

// ---------------- launch -----------------------------------------------------
extern "C" void kernel_launch(void* const* d_in, const int* in_sizes, int n_in,
                              void* d_out, int out_size)
{
    const float* x    = (const float*)d_in[0];
    const float* Wq   = (const float*)d_in[1];
    const float* Wk   = (const float*)d_in[2];
    const float* Wv   = (const float*)d_in[3];
    const float* Wo   = (const float*)d_in[4];
    const float* bo   = (const float*)d_in[5];
    const float* proj = (const float*)d_in[6];

    float *q, *k, *v, *om, *ksum;
    cudaGetSymbolAddress((void**)&q,    g_q);
    cudaGetSymbolAddress((void**)&k,    g_k);
    cudaGetSymbolAddress((void**)&v,    g_v);
    cudaGetSymbolAddress((void**)&om,   g_om);
    cudaGetSymbolAddress((void**)&ksum, g_ksum);

    const int M = BB * NN;   // 16384

    dim3 gBig(CC / 128, M / 128);   // (8, 128)
    sgemm128<<<gBig, 256>>>(x, Wq, nullptr, q, M, CC, CC);
    sgemm128<<<gBig, 256>>>(x, Wk, nullptr, k, M, CC, CC);
    sgemm128<<<gBig, 256>>>(x, Wv, nullptr, v, M, CC, CC);

    featmap_kernel<<<dim3(5, NN / 64, 2 * BHN), 256>>>(proj);

    cudaMemsetAsync(ksum, 0, BHN * RR * sizeof(float));
    ksum_kernel<<<dim3(BHN, 3, NN / 256), 128>>>();

    dinv_kernel<<<(BHN * NN) / 8, 256>>>();

    kv_kernel<<<dim3(BHN, 5), 256>>>();

    qkv_kernel<<<dim3(BHN, NN / 64), 256>>>();

    sgemm128<<<gBig, 256>>>(om, Wo, bo, (float*)d_out, M, CC, CC);
}